// round 15
// baseline (speedup 1.0000x reference)
#include <cuda_runtime.h>
#include <math.h>

// Problem dims
#define BB   128
#define NN   32
#define OBSD 128
#define AD   16
#define HH   4
#define DMD  128
#define ED   32
#define OAD  144
#define F1D  64
#define FIND 16
#define V0   (BB*NN*NN*FIND)   // weights start offset in d_out (value first, weights second)

// Scratch (device globals — no allocation allowed)
__device__ float g_aproj[BB*HH*NN*F1D];   // av_act @ W_f1_h
__device__ float g_dproj[BB*HH*NN*F1D];   // (av_pol-av_act) @ W_f1_h
__device__ float g_w    [BB*HH*NN*NN];    // mirror of attention weights (replay-stable)
__device__ float g_M [HH*DMD*DMD];        // (W_q W_k^T) / sqrt(DM) per head
__device__ float g_v2[HH*DMD];            // (W_k b_q) / sqrt(DM) per head
__device__ unsigned int g_done;           // prep completion counter (monotonic)
__device__ unsigned int g_bdone[BB];      // per-batch producer counters (monotonic)

__device__ __forceinline__ float lrelu(float x) { return x > 0.f ? x : 0.01f * x; }

// ---- packed f32x2 helpers (sm_103a FFMA2) ----
typedef unsigned long long u64;
__device__ __forceinline__ void ffma2(u64& d, u64 a, u64 b) {
    asm("fma.rn.f32x2 %0, %1, %2, %0;" : "+l"(d) : "l"(a), "l"(b));
}
__device__ __forceinline__ u64 dup2(float x) {
    u64 r; asm("mov.b64 %0, {%1, %1};" : "=l"(r) : "f"(x)); return r;
}
__device__ __forceinline__ u64 pack2(float lo, float hi) {
    u64 r; asm("mov.b64 %0, {%1, %2};" : "=l"(r) : "f"(lo), "f"(hi)); return r;
}
__device__ __forceinline__ float2 unpk2(u64 v) {
    float lo, hi; asm("mov.b64 {%0, %1}, %2;" : "=f"(lo), "=f"(hi) : "l"(v));
    return make_float2(lo, hi);
}

#define INV_SQRT_DM 0.08838834764831845f
#define N_PREP 256
#define N_PROD (BB*HH)       // 512 merged producers (one per (b,h))
#define N_CONS (BB*4)        // 512

// ---------------------------------------------------------------------------
// ONE kernel, three roles by bid range:
//   [0,256)      prep: g_M/g_v2
//   [256,768)    merged producer per (b,h): sap phase THEN attention phase
//                (states tile loaded/transposed once, smem aliased by phase)
//   [768,1280)   consumer: spins g_bdone[b]>=4, then fused MLP
// Peak smem 16768 floats (65.5KB) -> 3 CTAs/SM. Same gates as R13/14.
// ---------------------------------------------------------------------------
#define K_SMEM_F (16768)

__global__ __launch_bounds__(256, 3)
void k_fused(const float* __restrict__ states,
             const float* __restrict__ policies,
             const float* __restrict__ actions,
             const float* __restrict__ W_se, const float* __restrict__ b_se,
             const float* __restrict__ W_q,  const float* __restrict__ b_q,
             const float* __restrict__ W_k,
             const float* __restrict__ W_sap, const float* __restrict__ b_sap,
             const float* __restrict__ W_av,  const float* __restrict__ b_av,
             const float* __restrict__ W_f1,  const float* __restrict__ b_f1,
             const float* __restrict__ W_f2,  const float* __restrict__ b_f2,
             float* __restrict__ out_w, float* __restrict__ val)
{
    extern __shared__ float sm[];
    const int tid = threadIdx.x;

    if (blockIdx.x < N_PREP) {
        // ================= prep: M_h = (W_q W_k^T)/sqrt(DM), v2 =============
        const int h  = blockIdx.x >> 6;
        const int rt = (blockIdx.x >> 2) & 15;
        const int ct = blockIdx.x & 3;
        float* BT = sm;   // [128][33]
        const int w    = tid >> 5;
        const int lane = tid & 31;

        {
            const float* src = W_k + (size_t)h * DMD * DMD + (size_t)ct * 32 * DMD;
            for (int i = tid; i < 32 * DMD; i += 256) {
                int dl = i >> 7, e = i & 127;
                BT[e * 33 + dl] = src[i];
            }
        }
        __syncthreads();

        const int d = rt * 8 + w;
        const float4* Arow = (const float4*)(W_q + (size_t)h * DMD * DMD + (size_t)d * DMD);

        float a0 = 0.f, a1 = 0.f, a2 = 0.f, a3 = 0.f;
        #pragma unroll 8
        for (int e4 = 0; e4 < 32; e4++) {
            float4 a = __ldg(Arow + e4);
            int eb = e4 * 4;
            a0 += a.x * BT[(eb + 0) * 33 + lane];
            a1 += a.y * BT[(eb + 1) * 33 + lane];
            a2 += a.z * BT[(eb + 2) * 33 + lane];
            a3 += a.w * BT[(eb + 3) * 33 + lane];
        }
        g_M[(size_t)h * DMD * DMD + (size_t)d * DMD + ct * 32 + lane] =
            ((a0 + a1) + (a2 + a3)) * INV_SQRT_DM;

        if (rt == 0 && w == 0) {
            const float* bq = b_q + h * DMD;
            float s0 = 0.f, s1 = 0.f, s2 = 0.f, s3 = 0.f;
            #pragma unroll 8
            for (int e = 0; e < DMD; e += 4) {
                s0 += BT[(e + 0) * 33 + lane] * __ldg(bq + e + 0);
                s1 += BT[(e + 1) * 33 + lane] * __ldg(bq + e + 1);
                s2 += BT[(e + 2) * 33 + lane] * __ldg(bq + e + 2);
                s3 += BT[(e + 3) * 33 + lane] * __ldg(bq + e + 3);
            }
            g_v2[h * DMD + ct * 32 + lane] = ((s0 + s1) + (s2 + s3)) * INV_SQRT_DM;
        }

        __threadfence();
        __syncthreads();
        if (tid == 0) atomicAdd(&g_done, 1u);
        return;
    }

    if (blockIdx.x >= N_PREP + N_PROD) {
        // ================= consumer (fused final MLP) =================
        const int cid     = blockIdx.x - (N_PREP + N_PROD);
        const int quarter = cid & 3;
        const int b       = cid >> 2;
        const int base_i  = quarter * 8;
        float* w4h = sm;           // [4][8][32]
        float* dpT = sm + 1024;    // [4][64][33]
        float* P   = sm + 9472;    // [8][64]
        float* wf2 = sm + 9984;    // [64][16]
        float* bf1 = sm + 11008;   // [64]
        float* bf2 = sm + 11072;   // [16]

        for (int i = tid; i < 1024; i += 256) wf2[i] = W_f2[i];
        if (tid < 64) bf1[tid] = b_f1[tid];
        if (tid < 16) bf2[tid] = b_f2[tid];

        if (tid == 0) {
            volatile unsigned int* p = &g_bdone[b];
            while (*p < 4u) { __nanosleep(64); }
            __threadfence();
        }
        __syncthreads();

        {
            const float* wg = g_w + (size_t)b * 4096;
            int e4 = tid * 4;
            int hh = e4 >> 8, il = (e4 >> 5) & 7, k = e4 & 31;
            *(float4*)(w4h + e4) =
                *(const float4*)(wg + ((size_t)hh * 32 + base_i + il) * 32 + k);
        }
        {
            const float* dp = g_dproj + (size_t)b * 8192;
            for (int i = tid; i < 8192; i += 256) {
                int hh = i >> 11, j = (i >> 6) & 31, u = i & 63;
                dpT[(hh * 64 + u) * 33 + j] = dp[i];
            }
        }
        __syncthreads();

        // ---- P[il][u] ----
        {
            const int u  = tid & 63;
            const int i0 = tid >> 6;
            const float* ap = g_aproj + (size_t)b * 8192;
            float p0 = bf1[u], p1 = p0;
            #pragma unroll 4
            for (int hk = 0; hk < 128; hk++) {
                int hh = hk >> 5, k = hk & 31;
                float av = __ldg(ap + (hh * 32 + k) * 64 + u);
                p0 += w4h[hh * 256 + (i0 * 2 + 0) * 32 + k] * av;
                p1 += w4h[hh * 256 + (i0 * 2 + 1) * 32 + k] * av;
            }
            P[(i0 * 2 + 0) * 64 + u] = p0;
            P[(i0 * 2 + 1) * 64 + u] = p1;
        }
        __syncthreads();

        // ---- fused per-(i,j) MLP (FFMA2) ----
        {
            const int il = tid >> 5;
            const int j  = tid & 31;
            float wr0 = w4h[0 * 256 + il * 32 + j];
            float wr1 = w4h[1 * 256 + il * 32 + j];
            float wr2 = w4h[2 * 256 + il * 32 + j];
            float wr3 = w4h[3 * 256 + il * 32 + j];
            u64 o2[8];
            #pragma unroll
            for (int k = 0; k < 8; k++) o2[k] = pack2(bf2[2 * k], bf2[2 * k + 1]);
            #pragma unroll 8
            for (int u = 0; u < 64; u++) {
                float t = P[il * 64 + u];
                t += wr0 * dpT[(0 * 64 + u) * 33 + j];
                t += wr1 * dpT[(1 * 64 + u) * 33 + j];
                t += wr2 * dpT[(2 * 64 + u) * 33 + j];
                t += wr3 * dpT[(3 * 64 + u) * 33 + j];
                u64 hd = dup2(lrelu(t));
                ulonglong2 wA = *(const ulonglong2*)(wf2 + u * 16 + 0);
                ulonglong2 wB = *(const ulonglong2*)(wf2 + u * 16 + 4);
                ulonglong2 wC = *(const ulonglong2*)(wf2 + u * 16 + 8);
                ulonglong2 wD = *(const ulonglong2*)(wf2 + u * 16 + 12);
                ffma2(o2[0], hd, wA.x); ffma2(o2[1], hd, wA.y);
                ffma2(o2[2], hd, wB.x); ffma2(o2[3], hd, wB.y);
                ffma2(o2[4], hd, wC.x); ffma2(o2[5], hd, wC.y);
                ffma2(o2[6], hd, wD.x); ffma2(o2[7], hd, wD.y);
            }
            float* dst = val + (((size_t)b * NN + base_i + il) * NN + j) * FIND;
            #pragma unroll
            for (int k = 0; k < 4; k++) {
                float2 lo = unpk2(o2[2 * k]);
                float2 hi = unpk2(o2[2 * k + 1]);
                *(float4*)(dst + 4 * k) = make_float4(lo.x, lo.y, hi.x, hi.y);
            }
        }
        return;
    }

    // ================= merged producer: (b,h) does sap THEN attention ======
    const int bid = blockIdx.x - N_PREP;    // 0..511
    const int h   = bid & 3;
    const int b   = bid >> 2;

    // phase-1 layout
    float* sT   = sm;            // [128][36] states o-major (lives through phase 2 se-GEMM)
    float* aT   = sm + 4608;     // [16][36]
    float* pT   = sm + 5184;     // [16][36]
    float* embT = sm + 5760;     // [128][68]
    float* avs  = sm + 14464;    // [64][36]
    float* wf1h = sm + 5760;     // [32][64] (alias embT after av phase)
    // phase-2 layout (after phase-1 done)
    float* seT  = sm + 4608;     // [128][36]
    float* seR  = sm + 9216;     // [32][132]
    float* tb   = sm;            // [32][132] (alias sT after se-GEMM)
    float* sc   = sm + 13440;    // [32][32]
    float* rv   = sm + 14464;    // [32]

    const float* sb = states + b * NN * OBSD;
    for (int i = tid; i < NN * OBSD; i += 256) {
        int n = i >> 7, o = i & 127;
        sT[o * 36 + n] = sb[i];
    }
    const float* ab = actions  + b * NN * AD;
    const float* pb = policies + b * NN * AD;
    for (int i = tid; i < NN * AD; i += 256) {
        int n = i >> 4, c = i & 15;
        aT[c * 36 + n] = ab[i];
        pT[c * 36 + n] = pb[i];
    }
    __syncthreads();

    const int tr = tid >> 5;
    const int tc = tid & 31;

    // ================= PHASE 1: sap -> Aproj/Dproj =================
    {
        const float* Wh = W_sap + (size_t)h * OAD * DMD;
        u64 acc2[4][2];
        #pragma unroll
        for (int c = 0; c < 4; c++) { acc2[c][0] = 0ull; acc2[c][1] = 0ull; }
        #pragma unroll 4
        for (int o = 0; o < OBSD; o++) {
            ulonglong2 ap = *(const ulonglong2*)(sT + o * 36 + 4 * tr);
            float4 w = __ldg((const float4*)(Wh + o * DMD + 4 * tc));
            u64 wd0 = dup2(w.x), wd1 = dup2(w.y), wd2 = dup2(w.z), wd3 = dup2(w.w);
            ffma2(acc2[0][0], ap.x, wd0); ffma2(acc2[0][1], ap.y, wd0);
            ffma2(acc2[1][0], ap.x, wd1); ffma2(acc2[1][1], ap.y, wd1);
            ffma2(acc2[2][0], ap.x, wd2); ffma2(acc2[2][1], ap.y, wd2);
            ffma2(acc2[3][0], ap.x, wd3); ffma2(acc2[3][1], ap.y, wd3);
        }
        float4 bs = __ldg((const float4*)(b_sap + h * DMD + 4 * tc));
        float bb4[4] = {bs.x, bs.y, bs.z, bs.w};

        // action tail + store
        {
            u64 accA[4][2];
            #pragma unroll
            for (int c = 0; c < 4; c++) { accA[c][0] = acc2[c][0]; accA[c][1] = acc2[c][1]; }
            #pragma unroll 4
            for (int c16 = 0; c16 < AD; c16++) {
                ulonglong2 ap = *(const ulonglong2*)(aT + c16 * 36 + 4 * tr);
                float4 w = __ldg((const float4*)(Wh + (size_t)(OBSD + c16) * DMD + 4 * tc));
                u64 wd0 = dup2(w.x), wd1 = dup2(w.y), wd2 = dup2(w.z), wd3 = dup2(w.w);
                ffma2(accA[0][0], ap.x, wd0); ffma2(accA[0][1], ap.y, wd0);
                ffma2(accA[1][0], ap.x, wd1); ffma2(accA[1][1], ap.y, wd1);
                ffma2(accA[2][0], ap.x, wd2); ffma2(accA[2][1], ap.y, wd2);
                ffma2(accA[3][0], ap.x, wd3); ffma2(accA[3][1], ap.y, wd3);
            }
            #pragma unroll
            for (int c = 0; c < 4; c++) {
                int d = 4 * tc + c;
                float2 r01 = unpk2(accA[c][0]);
                float2 r23 = unpk2(accA[c][1]);
                embT[d * 68 + 4 * tr + 0] = lrelu(r01.x + bb4[c]);
                embT[d * 68 + 4 * tr + 1] = lrelu(r01.y + bb4[c]);
                embT[d * 68 + 4 * tr + 2] = lrelu(r23.x + bb4[c]);
                embT[d * 68 + 4 * tr + 3] = lrelu(r23.y + bb4[c]);
            }
        }
        // policy tail + store
        {
            #pragma unroll 4
            for (int c16 = 0; c16 < AD; c16++) {
                ulonglong2 ap = *(const ulonglong2*)(pT + c16 * 36 + 4 * tr);
                float4 w = __ldg((const float4*)(Wh + (size_t)(OBSD + c16) * DMD + 4 * tc));
                u64 wd0 = dup2(w.x), wd1 = dup2(w.y), wd2 = dup2(w.z), wd3 = dup2(w.w);
                ffma2(acc2[0][0], ap.x, wd0); ffma2(acc2[0][1], ap.y, wd0);
                ffma2(acc2[1][0], ap.x, wd1); ffma2(acc2[1][1], ap.y, wd1);
                ffma2(acc2[2][0], ap.x, wd2); ffma2(acc2[2][1], ap.y, wd2);
                ffma2(acc2[3][0], ap.x, wd3); ffma2(acc2[3][1], ap.y, wd3);
            }
            #pragma unroll
            for (int c = 0; c < 4; c++) {
                int d = 4 * tc + c;
                float2 r01 = unpk2(acc2[c][0]);
                float2 r23 = unpk2(acc2[c][1]);
                embT[d * 68 + 32 + 4 * tr + 0] = lrelu(r01.x + bb4[c]);
                embT[d * 68 + 32 + 4 * tr + 1] = lrelu(r01.y + bb4[c]);
                embT[d * 68 + 32 + 4 * tr + 2] = lrelu(r23.x + bb4[c]);
                embT[d * 68 + 32 + 4 * tr + 3] = lrelu(r23.y + bb4[c]);
            }
        }
    }
    __syncthreads();

    // ---- av (64 x 32) [FFMA2] -> avs ----
    {
        const int tr2 = tid >> 4;
        const int tc2 = tid & 15;
        const float* Wh = W_av + (size_t)h * DMD * ED;
        u64 acc2[2][2];
        acc2[0][0] = 0ull; acc2[0][1] = 0ull;
        acc2[1][0] = 0ull; acc2[1][1] = 0ull;
        #pragma unroll 4
        for (int d = 0; d < DMD; d++) {
            ulonglong2 ap = *(const ulonglong2*)(embT + d * 68 + 4 * tr2);
            float2 w = __ldg((const float2*)(Wh + d * ED + 2 * tc2));
            u64 wd0 = dup2(w.x), wd1 = dup2(w.y);
            ffma2(acc2[0][0], ap.x, wd0); ffma2(acc2[0][1], ap.y, wd0);
            ffma2(acc2[1][0], ap.x, wd1); ffma2(acc2[1][1], ap.y, wd1);
        }
        float2 bv = __ldg((const float2*)(b_av + h * ED + 2 * tc2));
        float bb2[2] = {bv.x, bv.y};
        #pragma unroll
        for (int c = 0; c < 2; c++) {
            float2 r01 = unpk2(acc2[c][0]);
            float2 r23 = unpk2(acc2[c][1]);
            avs[(4 * tr2 + 0) * 36 + 2 * tc2 + c] = lrelu(r01.x + bb2[c]);
            avs[(4 * tr2 + 1) * 36 + 2 * tc2 + c] = lrelu(r01.y + bb2[c]);
            avs[(4 * tr2 + 2) * 36 + 2 * tc2 + c] = lrelu(r23.x + bb2[c]);
            avs[(4 * tr2 + 3) * 36 + 2 * tc2 + c] = lrelu(r23.y + bb2[c]);
        }
    }
    __syncthreads();   // embT dead -> wf1h may overwrite

    {
        const float4* src = (const float4*)(W_f1 + (size_t)h * ED * F1D);
        float4* dst = (float4*)wf1h;
        for (int i = tid; i < ED * F1D / 4; i += 256) dst[i] = src[i];
    }
    __syncthreads();

    // ---- Aproj / Dproj ----
    {
        const int u  = tid & 63;
        const int i0 = tid >> 6;
        #pragma unroll
        for (int r = 0; r < 8; r++) {
            int j = i0 * 8 + r;
            float pa = 0.f, pd = 0.f;
            #pragma unroll 4
            for (int e = 0; e < ED; e++) {
                float aa = avs[j * 36 + e];
                float dd = avs[(32 + j) * 36 + e] - aa;
                float wv = wf1h[e * F1D + u];
                pa += aa * wv;
                pd += dd * wv;
            }
            size_t o = ((size_t)(b * HH + h) * NN + j) * F1D + u;
            g_aproj[o] = pa;
            g_dproj[o] = pd;
        }
    }
    __syncthreads();   // phase-1 smem (except sT) dead; phase 2 may overwrite

    // ================= PHASE 2: attention weights =================
    // ---- se = leaky(states @ W_se + b_se) [FFMA2] ----
    {
        const float* Wh = W_se + (size_t)h * OBSD * DMD;
        u64 acc2[4][2];
        #pragma unroll
        for (int c = 0; c < 4; c++) { acc2[c][0] = 0ull; acc2[c][1] = 0ull; }
        #pragma unroll 4
        for (int o = 0; o < OBSD; o++) {
            ulonglong2 ap = *(const ulonglong2*)(sT + o * 36 + 4 * tr);
            float4 w = __ldg((const float4*)(Wh + o * DMD + 4 * tc));
            u64 wd0 = dup2(w.x), wd1 = dup2(w.y), wd2 = dup2(w.z), wd3 = dup2(w.w);
            ffma2(acc2[0][0], ap.x, wd0); ffma2(acc2[0][1], ap.y, wd0);
            ffma2(acc2[1][0], ap.x, wd1); ffma2(acc2[1][1], ap.y, wd1);
            ffma2(acc2[2][0], ap.x, wd2); ffma2(acc2[2][1], ap.y, wd2);
            ffma2(acc2[3][0], ap.x, wd3); ffma2(acc2[3][1], ap.y, wd3);
        }
        float4 bs = __ldg((const float4*)(b_se + h * DMD + 4 * tc));
        float bb4[4] = {bs.x, bs.y, bs.z, bs.w};
        #pragma unroll
        for (int c = 0; c < 4; c++) {
            int d = 4 * tc + c;
            float2 r01 = unpk2(acc2[c][0]);
            float2 r23 = unpk2(acc2[c][1]);
            float v0 = lrelu(r01.x + bb4[c]);
            float v1 = lrelu(r01.y + bb4[c]);
            float v2 = lrelu(r23.x + bb4[c]);
            float v3 = lrelu(r23.y + bb4[c]);
            seT[d * 36 + 4 * tr + 0] = v0;
            seT[d * 36 + 4 * tr + 1] = v1;
            seT[d * 36 + 4 * tr + 2] = v2;
            seT[d * 36 + 4 * tr + 3] = v3;
            seR[(4 * tr + 0) * 132 + d] = v0;
            seR[(4 * tr + 1) * 132 + d] = v1;
            seR[(4 * tr + 2) * 132 + d] = v2;
            seR[(4 * tr + 3) * 132 + d] = v3;
        }
    }

    // ---- wait for prep (g_M/g_v2) — long hidden by phase 1 ----
    if (tid == 0) {
        volatile unsigned int* p = &g_done;
        while (*p < N_PREP) { __nanosleep(64); }
    }
    __syncthreads();   // also orders se stores (and sT death) before t-GEMM/tb

    // ---- t = se @ M_h [FFMA2] -> tb (aliases sT) ----
    {
        const float* Mh = g_M + (size_t)h * DMD * DMD;
        u64 acc2[4][2];
        #pragma unroll
        for (int c = 0; c < 4; c++) { acc2[c][0] = 0ull; acc2[c][1] = 0ull; }
        #pragma unroll 4
        for (int d = 0; d < DMD; d++) {
            ulonglong2 ap = *(const ulonglong2*)(seT + d * 36 + 4 * tr);
            float4 w = __ldg((const float4*)(Mh + (size_t)d * DMD + 4 * tc));
            u64 wd0 = dup2(w.x), wd1 = dup2(w.y), wd2 = dup2(w.z), wd3 = dup2(w.w);
            ffma2(acc2[0][0], ap.x, wd0); ffma2(acc2[0][1], ap.y, wd0);
            ffma2(acc2[1][0], ap.x, wd1); ffma2(acc2[1][1], ap.y, wd1);
            ffma2(acc2[2][0], ap.x, wd2); ffma2(acc2[2][1], ap.y, wd2);
            ffma2(acc2[3][0], ap.x, wd3); ffma2(acc2[3][1], ap.y, wd3);
        }
        float tv[4][4];
        #pragma unroll
        for (int c = 0; c < 4; c++) {
            float2 r01 = unpk2(acc2[c][0]);
            float2 r23 = unpk2(acc2[c][1]);
            tv[0][c] = r01.x; tv[1][c] = r01.y;
            tv[2][c] = r23.x; tv[3][c] = r23.y;
        }
        #pragma unroll
        for (int r = 0; r < 4; r++)
            *(float4*)(tb + (4 * tr + r) * 132 + 4 * tc) =
                make_float4(tv[r][0], tv[r][1], tv[r][2], tv[r][3]);
    }
    if (tid < 128) {
        const int j = tid >> 2, part = tid & 3;
        const float* v2 = g_v2 + h * DMD;
        float s = 0.f;
        #pragma unroll 8
        for (int e = part * 32; e < part * 32 + 32; e++)
            s += v2[e] * seR[j * 132 + e];
        s += __shfl_xor_sync(0xffffffffu, s, 1);
        s += __shfl_xor_sync(0xffffffffu, s, 2);
        if (part == 0) rv[j] = s;
    }
    __syncthreads();

    // ---- scores [FFMA2 dot products] ----
    {
        const int i  = tid >> 3;
        const int j0 = (tid & 7) * 4;
        u64 s2[4] = {0ull, 0ull, 0ull, 0ull};
        #pragma unroll 4
        for (int e = 0; e < DMD; e += 4) {
            ulonglong2 qv = *(const ulonglong2*)(tb + i * 132 + e);
            #pragma unroll
            for (int jj = 0; jj < 4; jj++) {
                ulonglong2 kv = *(const ulonglong2*)(seR + (j0 + jj) * 132 + e);
                ffma2(s2[jj], qv.x, kv.x);
                ffma2(s2[jj], qv.y, kv.y);
            }
        }
        #pragma unroll
        for (int jj = 0; jj < 4; jj++) {
            float2 p = unpk2(s2[jj]);
            sc[i * 32 + j0 + jj] = p.x + p.y + rv[j0 + jj];
        }
    }
    __syncthreads();

    // ---- softmax -> d_out tail AND g_w mirror ----
    {
        const int lane = tid & 31, wp = tid >> 5;
        float* dst = out_w + ((size_t)(b * HH + h) * NN) * NN;
        float* mir = g_w   + ((size_t)(b * HH + h) * NN) * NN;
        #pragma unroll
        for (int rr = 0; rr < 4; rr++) {
            int i = wp * 4 + rr;
            float v = sc[i * 32 + lane];
            float m = v;
            #pragma unroll
            for (int off = 16; off > 0; off >>= 1)
                m = fmaxf(m, __shfl_xor_sync(0xffffffffu, m, off));
            float e = __expf(v - m);
            float s = e;
            #pragma unroll
            for (int off = 16; off > 0; off >>= 1)
                s += __shfl_xor_sync(0xffffffffu, s, off);
            float wv = e / s;
            dst[i * NN + lane] = wv;
            mir[i * NN + lane] = wv;
        }
    }
    __threadfence();
    __syncthreads();
    if (tid == 0) atomicAdd(&g_bdone[b], 1u);
}

// ---------------------------------------------------------------------------
extern "C" void kernel_launch(void* const* d_in, const int* in_sizes, int n_in,
                              void* d_out, int out_size)
{
    (void)in_sizes; (void)n_in; (void)out_size;
    const float* states   = (const float*)d_in[0];
    const float* policies = (const float*)d_in[1];
    const float* actions  = (const float*)d_in[2];
    const float* W_se  = (const float*)d_in[3];  const float* b_se = (const float*)d_in[4];
    const float* W_k   = (const float*)d_in[5];  const float* b_k  = (const float*)d_in[6];
    const float* W_q   = (const float*)d_in[7];  const float* b_q  = (const float*)d_in[8];
    const float* W_sap = (const float*)d_in[9];  const float* b_sap= (const float*)d_in[10];
    const float* W_av  = (const float*)d_in[11]; const float* b_av = (const float*)d_in[12];
    const float* W_f1  = (const float*)d_in[13]; const float* b_f1 = (const float*)d_in[14];
    const float* W_f2  = (const float*)d_in[15]; const float* b_f2 = (const float*)d_in[16];
    (void)b_k;
    float* out   = (float*)d_out;
    float* out_w = out + V0;

    cudaFuncSetAttribute(k_fused, cudaFuncAttributeMaxDynamicSharedMemorySize, K_SMEM_F * 4);

    k_fused<<<N_PREP + N_PROD + N_CONS, 256, K_SMEM_F * 4>>>(
        states, policies, actions,
        W_se, b_se, W_q, b_q, W_k,
        W_sap, b_sap, W_av, b_av,
        W_f1, b_f1, W_f2, b_f2,
        out_w, out);
}

// round 16
// speedup vs baseline: 1.0576x; 1.0576x over previous
#include <cuda_runtime.h>
#include <math.h>

// Problem dims
#define BB   128
#define NN   32
#define OBSD 128
#define AD   16
#define HH   4
#define DMD  128
#define ED   32
#define OAD  144
#define F1D  64
#define FIND 16
#define V0   (BB*NN*NN*FIND)   // weights start offset in d_out (value first, weights second)

// Scratch (device globals — no allocation allowed)
__device__ float g_aproj[BB*HH*NN*F1D];   // av_act @ W_f1_h
__device__ float g_dproj[BB*HH*NN*F1D];   // (av_pol-av_act) @ W_f1_h
__device__ float g_w    [BB*HH*NN*NN];    // mirror of attention weights (replay-stable)
__device__ float g_M [HH*DMD*DMD];        // (W_q W_k^T) / sqrt(DM) per head
__device__ float g_v2[HH*DMD];            // (W_k b_q) / sqrt(DM) per head
__device__ unsigned int g_done;           // prep completion counter (monotonic)
__device__ unsigned int g_bdone[BB];      // per-batch producer counters (monotonic)

__device__ __forceinline__ float lrelu(float x) { return x > 0.f ? x : 0.01f * x; }

// ---- packed f32x2 helpers (sm_103a FFMA2) ----
typedef unsigned long long u64;
__device__ __forceinline__ void ffma2(u64& d, u64 a, u64 b) {
    asm("fma.rn.f32x2 %0, %1, %2, %0;" : "+l"(d) : "l"(a), "l"(b));
}
__device__ __forceinline__ u64 dup2(float x) {
    u64 r; asm("mov.b64 %0, {%1, %1};" : "=l"(r) : "f"(x)); return r;
}
__device__ __forceinline__ u64 pack2(float lo, float hi) {
    u64 r; asm("mov.b64 %0, {%1, %2};" : "=l"(r) : "f"(lo), "f"(hi)); return r;
}
__device__ __forceinline__ float2 unpk2(u64 v) {
    float lo, hi; asm("mov.b64 {%0, %1}, %2;" : "=f"(lo), "=f"(hi) : "l"(v));
    return make_float2(lo, hi);
}

#define INV_SQRT_DM 0.08838834764831845f
#define N_PREP 256
#define N_ROLE (BB*HH*2)     // 1024
#define N_CONS (BB*2)        // 256 consumers, 16 i-rows each

// ---------------------------------------------------------------------------
// ONE kernel, three roles by bid range (R14 structure; consumers halved):
//   [0,256) prep | [256,1280) producers | [1280,1536) consumers (gated)
// smem = 18720 floats (74.9KB) -> 3 CTAs/SM.
// ---------------------------------------------------------------------------
#define K12_SMEM_F (18720)

__global__ __launch_bounds__(256, 3)
void k_fused(const float* __restrict__ states,
             const float* __restrict__ policies,
             const float* __restrict__ actions,
             const float* __restrict__ W_se, const float* __restrict__ b_se,
             const float* __restrict__ W_q,  const float* __restrict__ b_q,
             const float* __restrict__ W_k,
             const float* __restrict__ W_sap, const float* __restrict__ b_sap,
             const float* __restrict__ W_av,  const float* __restrict__ b_av,
             const float* __restrict__ W_f1,  const float* __restrict__ b_f1,
             const float* __restrict__ W_f2,  const float* __restrict__ b_f2,
             float* __restrict__ out_w, float* __restrict__ val)
{
    extern __shared__ float sm[];
    const int tid = threadIdx.x;

    if (blockIdx.x < N_PREP) {
        // ================= prep: M_h = (W_q W_k^T)/sqrt(DM), v2 =============
        const int h  = blockIdx.x >> 6;
        const int rt = (blockIdx.x >> 2) & 15;
        const int ct = blockIdx.x & 3;
        float* BT = sm;   // [128][33]
        const int w    = tid >> 5;
        const int lane = tid & 31;

        {
            const float* src = W_k + (size_t)h * DMD * DMD + (size_t)ct * 32 * DMD;
            for (int i = tid; i < 32 * DMD; i += 256) {
                int dl = i >> 7, e = i & 127;
                BT[e * 33 + dl] = src[i];
            }
        }
        __syncthreads();

        const int d = rt * 8 + w;
        const float4* Arow = (const float4*)(W_q + (size_t)h * DMD * DMD + (size_t)d * DMD);

        float a0 = 0.f, a1 = 0.f, a2 = 0.f, a3 = 0.f;
        #pragma unroll 8
        for (int e4 = 0; e4 < 32; e4++) {
            float4 a = __ldg(Arow + e4);
            int eb = e4 * 4;
            a0 += a.x * BT[(eb + 0) * 33 + lane];
            a1 += a.y * BT[(eb + 1) * 33 + lane];
            a2 += a.z * BT[(eb + 2) * 33 + lane];
            a3 += a.w * BT[(eb + 3) * 33 + lane];
        }
        g_M[(size_t)h * DMD * DMD + (size_t)d * DMD + ct * 32 + lane] =
            ((a0 + a1) + (a2 + a3)) * INV_SQRT_DM;

        if (rt == 0 && w == 0) {
            const float* bq = b_q + h * DMD;
            float s0 = 0.f, s1 = 0.f, s2 = 0.f, s3 = 0.f;
            #pragma unroll 8
            for (int e = 0; e < DMD; e += 4) {
                s0 += BT[(e + 0) * 33 + lane] * __ldg(bq + e + 0);
                s1 += BT[(e + 1) * 33 + lane] * __ldg(bq + e + 1);
                s2 += BT[(e + 2) * 33 + lane] * __ldg(bq + e + 2);
                s3 += BT[(e + 3) * 33 + lane] * __ldg(bq + e + 3);
            }
            g_v2[h * DMD + ct * 32 + lane] = ((s0 + s1) + (s2 + s3)) * INV_SQRT_DM;
        }

        __threadfence();
        __syncthreads();
        if (tid == 0) atomicAdd(&g_done, 1u);
        return;
    }

    if (blockIdx.x >= N_PREP + N_ROLE) {
        // ================= consumer: 16 i-rows per block =================
        const int cid    = blockIdx.x - (N_PREP + N_ROLE);
        const int half   = cid & 1;
        const int b      = cid >> 1;
        const int base_i = half * 16;
        float* w4h = sm;           // [4][16][32]
        float* dpT = sm + 2048;    // [4][64][33]
        float* P   = sm + 10496;   // [16][64]
        float* wf2 = sm + 11520;   // [64][16]
        float* bf1 = sm + 12544;   // [64]
        float* bf2 = sm + 12608;   // [16]

        for (int i = tid; i < 1024; i += 256) wf2[i] = W_f2[i];
        if (tid < 64) bf1[tid] = b_f1[tid];
        if (tid < 16) bf2[tid] = b_f2[tid];

        if (tid == 0) {
            volatile unsigned int* p = &g_bdone[b];
            while (*p < 8u) { __nanosleep(64); }
            __threadfence();
        }
        __syncthreads();

        {   // weight rows for our 16 i per head: [4][16][32] = 512 float4
            const float* wg = g_w + (size_t)b * 4096;
            for (int i = tid; i < 512; i += 256) {
                int e4 = i * 4;
                int hh = e4 >> 9, rem = e4 & 511;
                int il = rem >> 5, k = rem & 31;
                *(float4*)(w4h + e4) =
                    *(const float4*)(wg + ((size_t)hh * 32 + base_i + il) * 32 + k);
            }
        }
        {
            const float* dp = g_dproj + (size_t)b * 8192;
            for (int i = tid; i < 8192; i += 256) {
                int hh = i >> 11, j = (i >> 6) & 31, u = i & 63;
                dpT[(hh * 64 + u) * 33 + j] = dp[i];
            }
        }
        __syncthreads();

        // ---- P[il][u]: 16 rows; aproj coalesced from L2 ----
        {
            const int u  = tid & 63;
            const int i0 = tid >> 6;   // 0..3 -> local rows i0*4..i0*4+3
            const float* ap = g_aproj + (size_t)b * 8192;
            float pacc[4];
            #pragma unroll
            for (int r = 0; r < 4; r++) pacc[r] = bf1[u];
            #pragma unroll 4
            for (int hk = 0; hk < 128; hk++) {
                int hh = hk >> 5, k = hk & 31;
                float av = __ldg(ap + (hh * 32 + k) * 64 + u);
                #pragma unroll
                for (int r = 0; r < 4; r++)
                    pacc[r] += w4h[hh * 512 + (i0 * 4 + r) * 32 + k] * av;
            }
            #pragma unroll
            for (int r = 0; r < 4; r++) P[(i0 * 4 + r) * 64 + u] = pacc[r];
        }
        __syncthreads();

        // ---- fused per-(i,j) MLP: 512 pairs, 2/thread (FFMA2) ----
        #pragma unroll
        for (int it = 0; it < 2; it++) {
            const int p  = tid + 256 * it;
            const int il = p >> 5;
            const int j  = p & 31;
            float wr0 = w4h[0 * 512 + il * 32 + j];
            float wr1 = w4h[1 * 512 + il * 32 + j];
            float wr2 = w4h[2 * 512 + il * 32 + j];
            float wr3 = w4h[3 * 512 + il * 32 + j];
            u64 o2[8];
            #pragma unroll
            for (int k = 0; k < 8; k++) o2[k] = pack2(bf2[2 * k], bf2[2 * k + 1]);
            #pragma unroll 8
            for (int u = 0; u < 64; u++) {
                float t = P[il * 64 + u];
                t += wr0 * dpT[(0 * 64 + u) * 33 + j];
                t += wr1 * dpT[(1 * 64 + u) * 33 + j];
                t += wr2 * dpT[(2 * 64 + u) * 33 + j];
                t += wr3 * dpT[(3 * 64 + u) * 33 + j];
                u64 hd = dup2(lrelu(t));
                ulonglong2 wA = *(const ulonglong2*)(wf2 + u * 16 + 0);
                ulonglong2 wB = *(const ulonglong2*)(wf2 + u * 16 + 4);
                ulonglong2 wC = *(const ulonglong2*)(wf2 + u * 16 + 8);
                ulonglong2 wD = *(const ulonglong2*)(wf2 + u * 16 + 12);
                ffma2(o2[0], hd, wA.x); ffma2(o2[1], hd, wA.y);
                ffma2(o2[2], hd, wB.x); ffma2(o2[3], hd, wB.y);
                ffma2(o2[4], hd, wC.x); ffma2(o2[5], hd, wC.y);
                ffma2(o2[6], hd, wD.x); ffma2(o2[7], hd, wD.y);
            }
            float* dst = val + (((size_t)b * NN + base_i + il) * NN + j) * FIND;
            #pragma unroll
            for (int k = 0; k < 4; k++) {
                float2 lo = unpk2(o2[2 * k]);
                float2 hi = unpk2(o2[2 * k + 1]);
                *(float4*)(dst + 4 * k) = make_float4(lo.x, lo.y, hi.x, hi.y);
            }
        }
        return;
    }

    const int bid  = blockIdx.x - N_PREP;
    const int role = bid & 1;
    const int idx  = bid >> 1;              // 0..511
    const int h    = idx & 3;
    const int b    = idx >> 2;

    if (role == 0) {
        // ================= attention weights =================
        float* sT  = sm;            // [128][36]
        float* seT = sm + 4608;     // [128][36]
        float* seR = sm + 9216;     // [32][132]
        float* tb  = sm + 13440;    // [32][132]
        float* sc  = sm + 17664;    // [32][32]
        float* rv  = sm + 18688;    // [32]

        const float* sb = states + b * NN * OBSD;
        for (int i = tid; i < NN * OBSD; i += 256) {
            int n = i >> 7, o = i & 127;
            sT[o * 36 + n] = sb[i];
        }
        __syncthreads();

        const int tr = tid >> 5;
        const int tc = tid & 31;

        // ---- se = leaky(states @ W_se + b_se) [FFMA2] ----
        {
            const float* Wh = W_se + (size_t)h * OBSD * DMD;
            u64 acc2[4][2];
            #pragma unroll
            for (int c = 0; c < 4; c++) { acc2[c][0] = 0ull; acc2[c][1] = 0ull; }
            #pragma unroll 4
            for (int o = 0; o < OBSD; o++) {
                ulonglong2 ap = *(const ulonglong2*)(sT + o * 36 + 4 * tr);
                float4 w = __ldg((const float4*)(Wh + o * DMD + 4 * tc));
                u64 wd0 = dup2(w.x), wd1 = dup2(w.y), wd2 = dup2(w.z), wd3 = dup2(w.w);
                ffma2(acc2[0][0], ap.x, wd0); ffma2(acc2[0][1], ap.y, wd0);
                ffma2(acc2[1][0], ap.x, wd1); ffma2(acc2[1][1], ap.y, wd1);
                ffma2(acc2[2][0], ap.x, wd2); ffma2(acc2[2][1], ap.y, wd2);
                ffma2(acc2[3][0], ap.x, wd3); ffma2(acc2[3][1], ap.y, wd3);
            }
            float4 bs = __ldg((const float4*)(b_se + h * DMD + 4 * tc));
            float bb4[4] = {bs.x, bs.y, bs.z, bs.w};
            #pragma unroll
            for (int c = 0; c < 4; c++) {
                int d = 4 * tc + c;
                float2 r01 = unpk2(acc2[c][0]);
                float2 r23 = unpk2(acc2[c][1]);
                float v0 = lrelu(r01.x + bb4[c]);
                float v1 = lrelu(r01.y + bb4[c]);
                float v2 = lrelu(r23.x + bb4[c]);
                float v3 = lrelu(r23.y + bb4[c]);
                seT[d * 36 + 4 * tr + 0] = v0;
                seT[d * 36 + 4 * tr + 1] = v1;
                seT[d * 36 + 4 * tr + 2] = v2;
                seT[d * 36 + 4 * tr + 3] = v3;
                seR[(4 * tr + 0) * 132 + d] = v0;
                seR[(4 * tr + 1) * 132 + d] = v1;
                seR[(4 * tr + 2) * 132 + d] = v2;
                seR[(4 * tr + 3) * 132 + d] = v3;
            }
        }

        // ---- wait for prep (g_M/g_v2) ----
        if (tid == 0) {
            volatile unsigned int* p = &g_done;
            while (*p < N_PREP) { __nanosleep(64); }
        }
        __syncthreads();

        // ---- t = se @ M_h [FFMA2] ----
        {
            const float* Mh = g_M + (size_t)h * DMD * DMD;
            u64 acc2[4][2];
            #pragma unroll
            for (int c = 0; c < 4; c++) { acc2[c][0] = 0ull; acc2[c][1] = 0ull; }
            #pragma unroll 4
            for (int d = 0; d < DMD; d++) {
                ulonglong2 ap = *(const ulonglong2*)(seT + d * 36 + 4 * tr);
                float4 w = __ldg((const float4*)(Mh + (size_t)d * DMD + 4 * tc));
                u64 wd0 = dup2(w.x), wd1 = dup2(w.y), wd2 = dup2(w.z), wd3 = dup2(w.w);
                ffma2(acc2[0][0], ap.x, wd0); ffma2(acc2[0][1], ap.y, wd0);
                ffma2(acc2[1][0], ap.x, wd1); ffma2(acc2[1][1], ap.y, wd1);
                ffma2(acc2[2][0], ap.x, wd2); ffma2(acc2[2][1], ap.y, wd2);
                ffma2(acc2[3][0], ap.x, wd3); ffma2(acc2[3][1], ap.y, wd3);
            }
            float tv[4][4];
            #pragma unroll
            for (int c = 0; c < 4; c++) {
                float2 r01 = unpk2(acc2[c][0]);
                float2 r23 = unpk2(acc2[c][1]);
                tv[0][c] = r01.x; tv[1][c] = r01.y;
                tv[2][c] = r23.x; tv[3][c] = r23.y;
            }
            #pragma unroll
            for (int r = 0; r < 4; r++)
                *(float4*)(tb + (4 * tr + r) * 132 + 4 * tc) =
                    make_float4(tv[r][0], tv[r][1], tv[r][2], tv[r][3]);
        }
        if (tid < 128) {
            const int j = tid >> 2, part = tid & 3;
            const float* v2 = g_v2 + h * DMD;
            float s = 0.f;
            #pragma unroll 8
            for (int e = part * 32; e < part * 32 + 32; e++)
                s += v2[e] * seR[j * 132 + e];
            s += __shfl_xor_sync(0xffffffffu, s, 1);
            s += __shfl_xor_sync(0xffffffffu, s, 2);
            if (part == 0) rv[j] = s;
        }
        __syncthreads();

        // ---- scores [FFMA2 dot products] ----
        {
            const int i  = tid >> 3;
            const int j0 = (tid & 7) * 4;
            u64 s2[4] = {0ull, 0ull, 0ull, 0ull};
            #pragma unroll 4
            for (int e = 0; e < DMD; e += 4) {
                ulonglong2 qv = *(const ulonglong2*)(tb + i * 132 + e);
                #pragma unroll
                for (int jj = 0; jj < 4; jj++) {
                    ulonglong2 kv = *(const ulonglong2*)(seR + (j0 + jj) * 132 + e);
                    ffma2(s2[jj], qv.x, kv.x);
                    ffma2(s2[jj], qv.y, kv.y);
                }
            }
            #pragma unroll
            for (int jj = 0; jj < 4; jj++) {
                float2 p = unpk2(s2[jj]);
                sc[i * 32 + j0 + jj] = p.x + p.y + rv[j0 + jj];
            }
        }
        __syncthreads();

        // ---- softmax -> d_out tail AND g_w mirror ----
        {
            const int lane = tid & 31, wp = tid >> 5;
            float* dst = out_w + ((size_t)(b * HH + h) * NN) * NN;
            float* mir = g_w   + ((size_t)(b * HH + h) * NN) * NN;
            #pragma unroll
            for (int rr = 0; rr < 4; rr++) {
                int i = wp * 4 + rr;
                float v = sc[i * 32 + lane];
                float m = v;
                #pragma unroll
                for (int off = 16; off > 0; off >>= 1)
                    m = fmaxf(m, __shfl_xor_sync(0xffffffffu, m, off));
                float e = __expf(v - m);
                float s = e;
                #pragma unroll
                for (int off = 16; off > 0; off >>= 1)
                    s += __shfl_xor_sync(0xffffffffu, s, off);
                float wv = e / s;
                dst[i * NN + lane] = wv;
                mir[i * NN + lane] = wv;
            }
        }
        __threadfence();
        __syncthreads();
        if (tid == 0) atomicAdd(&g_bdone[b], 1u);
    } else {
        // ================= sap embeddings -> Aproj/Dproj =================
        float* sT   = sm;            // [128][36]
        float* aT   = sm + 4608;     // [16][36]
        float* pT   = sm + 5184;     // [16][36]
        float* embT = sm + 5760;     // [128][68]
        float* avs  = sm;            // [64][36]  (aliases sT after emb)
        float* wf1h = sm + 5760;     // [32][64]  (aliases embT after av)

        const float* sb = states + b * NN * OBSD;
        for (int i = tid; i < NN * OBSD; i += 256) {
            int n = i >> 7, o = i & 127;
            sT[o * 36 + n] = sb[i];
        }
        const float* ab = actions  + b * NN * AD;
        const float* pb = policies + b * NN * AD;
        for (int i = tid; i < NN * AD; i += 256) {
            int n = i >> 4, c = i & 15;
            aT[c * 36 + n] = ab[i];
            pT[c * 36 + n] = pb[i];
        }
        __syncthreads();

        const int tr = tid >> 5;
        const int tc = tid & 31;

        // ---- sp + tails -> emb [FFMA2] ----
        {
            const float* Wh = W_sap + (size_t)h * OAD * DMD;
            u64 acc2[4][2];
            #pragma unroll
            for (int c = 0; c < 4; c++) { acc2[c][0] = 0ull; acc2[c][1] = 0ull; }
            #pragma unroll 4
            for (int o = 0; o < OBSD; o++) {
                ulonglong2 ap = *(const ulonglong2*)(sT + o * 36 + 4 * tr);
                float4 w = __ldg((const float4*)(Wh + o * DMD + 4 * tc));
                u64 wd0 = dup2(w.x), wd1 = dup2(w.y), wd2 = dup2(w.z), wd3 = dup2(w.w);
                ffma2(acc2[0][0], ap.x, wd0); ffma2(acc2[0][1], ap.y, wd0);
                ffma2(acc2[1][0], ap.x, wd1); ffma2(acc2[1][1], ap.y, wd1);
                ffma2(acc2[2][0], ap.x, wd2); ffma2(acc2[2][1], ap.y, wd2);
                ffma2(acc2[3][0], ap.x, wd3); ffma2(acc2[3][1], ap.y, wd3);
            }
            float4 bs = __ldg((const float4*)(b_sap + h * DMD + 4 * tc));
            float bb4[4] = {bs.x, bs.y, bs.z, bs.w};

            // action tail + store
            {
                u64 accA[4][2];
                #pragma unroll
                for (int c = 0; c < 4; c++) { accA[c][0] = acc2[c][0]; accA[c][1] = acc2[c][1]; }
                #pragma unroll 4
                for (int c16 = 0; c16 < AD; c16++) {
                    ulonglong2 ap = *(const ulonglong2*)(aT + c16 * 36 + 4 * tr);
                    float4 w = __ldg((const float4*)(Wh + (size_t)(OBSD + c16) * DMD + 4 * tc));
                    u64 wd0 = dup2(w.x), wd1 = dup2(w.y), wd2 = dup2(w.z), wd3 = dup2(w.w);
                    ffma2(accA[0][0], ap.x, wd0); ffma2(accA[0][1], ap.y, wd0);
                    ffma2(accA[1][0], ap.x, wd1); ffma2(accA[1][1], ap.y, wd1);
                    ffma2(accA[2][0], ap.x, wd2); ffma2(accA[2][1], ap.y, wd2);
                    ffma2(accA[3][0], ap.x, wd3); ffma2(accA[3][1], ap.y, wd3);
                }
                #pragma unroll
                for (int c = 0; c < 4; c++) {
                    int d = 4 * tc + c;
                    float2 r01 = unpk2(accA[c][0]);
                    float2 r23 = unpk2(accA[c][1]);
                    embT[d * 68 + 4 * tr + 0] = lrelu(r01.x + bb4[c]);
                    embT[d * 68 + 4 * tr + 1] = lrelu(r01.y + bb4[c]);
                    embT[d * 68 + 4 * tr + 2] = lrelu(r23.x + bb4[c]);
                    embT[d * 68 + 4 * tr + 3] = lrelu(r23.y + bb4[c]);
                }
            }
            // policy tail + store (accumulate into base acc2; dead after)
            {
                #pragma unroll 4
                for (int c16 = 0; c16 < AD; c16++) {
                    ulonglong2 ap = *(const ulonglong2*)(pT + c16 * 36 + 4 * tr);
                    float4 w = __ldg((const float4*)(Wh + (size_t)(OBSD + c16) * DMD + 4 * tc));
                    u64 wd0 = dup2(w.x), wd1 = dup2(w.y), wd2 = dup2(w.z), wd3 = dup2(w.w);
                    ffma2(acc2[0][0], ap.x, wd0); ffma2(acc2[0][1], ap.y, wd0);
                    ffma2(acc2[1][0], ap.x, wd1); ffma2(acc2[1][1], ap.y, wd1);
                    ffma2(acc2[2][0], ap.x, wd2); ffma2(acc2[2][1], ap.y, wd2);
                    ffma2(acc2[3][0], ap.x, wd3); ffma2(acc2[3][1], ap.y, wd3);
                }
                #pragma unroll
                for (int c = 0; c < 4; c++) {
                    int d = 4 * tc + c;
                    float2 r01 = unpk2(acc2[c][0]);
                    float2 r23 = unpk2(acc2[c][1]);
                    embT[d * 68 + 32 + 4 * tr + 0] = lrelu(r01.x + bb4[c]);
                    embT[d * 68 + 32 + 4 * tr + 1] = lrelu(r01.y + bb4[c]);
                    embT[d * 68 + 32 + 4 * tr + 2] = lrelu(r23.x + bb4[c]);
                    embT[d * 68 + 32 + 4 * tr + 3] = lrelu(r23.y + bb4[c]);
                }
            }
        }
        __syncthreads();

        // ---- av (64 x 32) [FFMA2] -> avs ----
        {
            const int tr2 = tid >> 4;
            const int tc2 = tid & 15;
            const float* Wh = W_av + (size_t)h * DMD * ED;
            u64 acc2[2][2];
            acc2[0][0] = 0ull; acc2[0][1] = 0ull;
            acc2[1][0] = 0ull; acc2[1][1] = 0ull;
            #pragma unroll 4
            for (int d = 0; d < DMD; d++) {
                ulonglong2 ap = *(const ulonglong2*)(embT + d * 68 + 4 * tr2);
                float2 w = __ldg((const float2*)(Wh + d * ED + 2 * tc2));
                u64 wd0 = dup2(w.x), wd1 = dup2(w.y);
                ffma2(acc2[0][0], ap.x, wd0); ffma2(acc2[0][1], ap.y, wd0);
                ffma2(acc2[1][0], ap.x, wd1); ffma2(acc2[1][1], ap.y, wd1);
            }
            float2 bv = __ldg((const float2*)(b_av + h * ED + 2 * tc2));
            float bb2[2] = {bv.x, bv.y};
            #pragma unroll
            for (int c = 0; c < 2; c++) {
                float2 r01 = unpk2(acc2[c][0]);
                float2 r23 = unpk2(acc2[c][1]);
                avs[(4 * tr2 + 0) * 36 + 2 * tc2 + c] = lrelu(r01.x + bb2[c]);
                avs[(4 * tr2 + 1) * 36 + 2 * tc2 + c] = lrelu(r01.y + bb2[c]);
                avs[(4 * tr2 + 2) * 36 + 2 * tc2 + c] = lrelu(r23.x + bb2[c]);
                avs[(4 * tr2 + 3) * 36 + 2 * tc2 + c] = lrelu(r23.y + bb2[c]);
            }
        }
        __syncthreads();

        {
            const float4* src = (const float4*)(W_f1 + (size_t)h * ED * F1D);
            float4* dst = (float4*)wf1h;
            for (int i = tid; i < ED * F1D / 4; i += 256) dst[i] = src[i];
        }
        __syncthreads();

        // ---- Aproj / Dproj ----
        {
            const int u  = tid & 63;
            const int i0 = tid >> 6;
            #pragma unroll
            for (int r = 0; r < 8; r++) {
                int j = i0 * 8 + r;
                float pa = 0.f, pd = 0.f;
                #pragma unroll 4
                for (int e = 0; e < ED; e++) {
                    float aa = avs[j * 36 + e];
                    float dd = avs[(32 + j) * 36 + e] - aa;
                    float wv = wf1h[e * F1D + u];
                    pa += aa * wv;
                    pd += dd * wv;
                }
                size_t o = ((size_t)(b * HH + h) * NN + j) * F1D + u;
                g_aproj[o] = pa;
                g_dproj[o] = pd;
            }
        }
        __threadfence();
        __syncthreads();
        if (tid == 0) atomicAdd(&g_bdone[b], 1u);
    }
}

// ---------------------------------------------------------------------------
extern "C" void kernel_launch(void* const* d_in, const int* in_sizes, int n_in,
                              void* d_out, int out_size)
{
    (void)in_sizes; (void)n_in; (void)out_size;
    const float* states   = (const float*)d_in[0];
    const float* policies = (const float*)d_in[1];
    const float* actions  = (const float*)d_in[2];
    const float* W_se  = (const float*)d_in[3];  const float* b_se = (const float*)d_in[4];
    const float* W_k   = (const float*)d_in[5];  const float* b_k  = (const float*)d_in[6];
    const float* W_q   = (const float*)d_in[7];  const float* b_q  = (const float*)d_in[8];
    const float* W_sap = (const float*)d_in[9];  const float* b_sap= (const float*)d_in[10];
    const float* W_av  = (const float*)d_in[11]; const float* b_av = (const float*)d_in[12];
    const float* W_f1  = (const float*)d_in[13]; const float* b_f1 = (const float*)d_in[14];
    const float* W_f2  = (const float*)d_in[15]; const float* b_f2 = (const float*)d_in[16];
    (void)b_k;
    float* out   = (float*)d_out;
    float* out_w = out + V0;

    cudaFuncSetAttribute(k_fused, cudaFuncAttributeMaxDynamicSharedMemorySize, K12_SMEM_F * 4);

    k_fused<<<N_PREP + N_ROLE + N_CONS, 256, K12_SMEM_F * 4>>>(
        states, policies, actions,
        W_se, b_se, W_q, b_q, W_k,
        W_sap, b_sap, W_av, b_av,
        W_f1, b_f1, W_f2, b_f2,
        out_w, out);
}